// round 8
// baseline (speedup 1.0000x reference)
#include <cuda_runtime.h>
#include <cuda_fp16.h>
#include <math.h>

#define NFEAT 18
#define NTRK  1500
#define BSZ   64
#define NTRACK (BSZ*NTRK)        // 96000
#define HID   256
#define TSTEPS 6
#define NT_TILE 64               // tracks per CTA (2 groups of 32)
#define CTA_THREADS 256

// output layout offsets (floats)
#define OUT_POS   24576000       // 96000*256
#define OUT_LOGPT 36864000       // + 96000*128
#define OUT_ETA   36960000
#define OUT_PHI   37056000

typedef unsigned long long u64;
typedef unsigned int u32;

// ---------------- device scratch: fragment-packed fp16 weights ----------------
// LSTM mats: ((((w*4 + g)*8 + kc)*32 + lane)*4 + reg)*2 + dd
__device__ __align__(16) __half P_hh0[65536];
__device__ __align__(16) __half P_ih1[65536];
__device__ __align__(16) __half P_hh1[65536];
__device__ __align__(16) __half P_w0 [32768];   // [8w][2mt][8kc][32][4][2]
__device__ __align__(16) __half P_w1 [65536];   // [8w][2kh][2mt][8kc][32][4][2]
__device__ __align__(16) float g_b0c[512];      // b_ih0+b_hh0, row = g*128+unit
__device__ __align__(16) float g_b1c[512];
__device__ float g_posmul[64];

// ---------------- prep: pack weights into mma fragment order ----------------
__global__ void prep_kernel(const float* __restrict__ W_hh0,
                            const float* __restrict__ b_ih0, const float* __restrict__ b_hh0,
                            const float* __restrict__ W_ih1, const float* __restrict__ W_hh1,
                            const float* __restrict__ b_ih1, const float* __restrict__ b_hh1,
                            const float* __restrict__ mw0,   const float* __restrict__ mw1)
{
    int stride = gridDim.x * blockDim.x;
    int idx0 = blockIdx.x * blockDim.x + threadIdx.x;

    // LSTM hh0 / ih1 / hh1: M-tile = gate (4 per warp), K=128 (8 kc)
    for (int i = idx0; i < 65536; i += stride) {
        int dd = i & 1, reg = (i >> 1) & 3, lane = (i >> 3) & 31;
        int kc = (i >> 8) & 7, g = (i >> 11) & 3, w = (i >> 13) & 7;
        int row = g * 128 + w * 16 + (lane >> 2) + 8 * (reg & 1);
        int col = kc * 16 + (lane & 3) * 2 + dd + 8 * (reg >> 1);
        P_hh0[i] = __float2half_rn(W_hh0[row * 128 + col]);
        P_ih1[i] = __float2half_rn(W_ih1[row * 128 + col]);
        P_hh1[i] = __float2half_rn(W_hh1[row * 128 + col]);
    }
    // MLP0, K=128 part (cols 3..130 of mw0)
    for (int i = idx0; i < 32768; i += stride) {
        int dd = i & 1, reg = (i >> 1) & 3, lane = (i >> 3) & 31;
        int kc = (i >> 8) & 7, mt = (i >> 11) & 1, w = (i >> 12) & 7;
        int row = w * 32 + mt * 16 + (lane >> 2) + 8 * (reg & 1);
        int k   = kc * 16 + (lane & 3) * 2 + dd + 8 * (reg >> 1);
        P_w0[i] = __float2half_rn(mw0[row * 131 + 3 + k]);
    }
    // MLP1, K=256, split into two K-halves (kh) of 8 kc each
    for (int i = idx0; i < 65536; i += stride) {
        int dd = i & 1, reg = (i >> 1) & 3, lane = (i >> 3) & 31;
        int kc = (i >> 8) & 7, mt = (i >> 11) & 1, kh = (i >> 12) & 1, w = (i >> 13) & 7;
        int row = w * 32 + mt * 16 + (lane >> 2) + 8 * (reg & 1);
        int k   = (kh * 8 + kc) * 16 + (lane & 3) * 2 + dd + 8 * (reg >> 1);
        P_w1[i] = __float2half_rn(mw1[row * 256 + k]);
    }
    for (int i = idx0; i < 512; i += stride) {
        g_b0c[i] = b_ih0[i] + b_hh0[i];
        g_b1c[i] = b_ih1[i] + b_hh1[i];
    }
    for (int i = idx0; i < 64; i += stride) {
        float e = (float)(2 * (i >> 1)) * (1.0f / 64.0f);
        g_posmul[i] = 6.283185307179586f / powf(10000.0f, e);
    }
}

// ---------------- activations (MUFU.TANH based) ----------------
__device__ __forceinline__ float tanh_mufu(float x) {
    float r; asm("tanh.approx.f32 %0, %1;" : "=f"(r) : "f"(x)); return r;
}
__device__ __forceinline__ float sigf(float x) {
    return fmaf(tanh_mufu(0.5f * x), 0.5f, 0.5f);
}

// ---------------- mma.sync wrapper ----------------
__device__ __forceinline__ void mma16816(float c[4], u32 a0, u32 a1, u32 a2, u32 a3,
                                         u32 b0, u32 b1) {
    asm("mma.sync.aligned.m16n8k16.row.col.f32.f16.f16.f32 "
        "{%0,%1,%2,%3}, {%4,%5,%6,%7}, {%8,%9}, {%0,%1,%2,%3};"
        : "+f"(c[0]), "+f"(c[1]), "+f"(c[2]), "+f"(c[3])
        : "r"(a0), "r"(a1), "r"(a2), "r"(a3), "r"(b0), "r"(b1));
}

// hB layout for 64-track buffers:
//   half_idx = ((kc*4 + c)*64 + n)*4 + kp*2 + dd,  unit u = kc*16 + 2c + dd + 8kp
__device__ __forceinline__ int hb64(int u, int n) {
    return ((u >> 4) * 4 + ((u & 7) >> 1)) * 256 + n * 4 + ((u >> 3) & 1) * 2 + (u & 1);
}

// fragment GEMM over one 32-track group: acc[MT][4nt][4] += Wpacked * B(hB, cols g32..g32+31)
template<int MT, int NKC>
__device__ __forceinline__ void gemm_frag(float acc[][4][4],
                                          const __half* __restrict__ pw,
                                          const __half* __restrict__ hB, int lane, int g32)
{
    const int c = lane & 3, colr = lane >> 2;
#pragma unroll
    for (int kc = 0; kc < NKC; ++kc) {
        u64 bv[4];
#pragma unroll
        for (int nt = 0; nt < 4; ++nt)
            bv[nt] = *reinterpret_cast<const u64*>(hB + ((kc * 4 + c) * 64 + g32 + nt * 8 + colr) * 4);
#pragma unroll
        for (int mt = 0; mt < MT; ++mt) {
            uint4 a = *reinterpret_cast<const uint4*>(pw + ((mt * NKC + kc) * 32 + lane) * 8);
#pragma unroll
            for (int nt = 0; nt < 4; ++nt)
                mma16816(acc[mt][nt], a.x, a.y, a.z, a.w,
                         (u32)bv[nt], (u32)(bv[nt] >> 32));
        }
    }
}

// ---------------- LSTM helpers ----------------
__device__ __forceinline__ void epi_lstm(float acc[4][4][4], float* cst, __half* hbuf,
                                         int g32, int w16, int lr, int c2)
{
#pragma unroll
    for (int nt = 0; nt < 4; ++nt)
#pragma unroll
        for (int idx = 0; idx < 4; ++idx) {
            float iv = sigf(acc[0][nt][idx]);
            float fv = sigf(acc[1][nt][idx]);
            float gv = tanh_mufu(acc[2][nt][idx]);
            float ov = sigf(acc[3][nt][idx]);
            float& cc = cst[nt * 4 + idx];
            cc = fv * cc + iv * gv;
            float h = ov * tanh_mufu(cc);
            int u = w16 + lr + 8 * (idx >> 1);
            int n = g32 + nt * 8 + c2 + (idx & 1);
            hbuf[hb64(u, n)] = __float2half_rn(h);
        }
}

// ---------------- fused LSTM + MLP (tensor-core, 2-group stagger) ----------------
__global__ void __launch_bounds__(CTA_THREADS, 1)
lstm_mlp_kernel(const float* __restrict__ tf,
                const float* __restrict__ W_ih0,   // [512][2] row-major
                const float* __restrict__ mw0,     // [256][131]
                const float* __restrict__ mb0,
                const float* __restrict__ mb1,
                float* __restrict__ out)
{
    const int tid  = threadIdx.x;
    const int lane = tid & 31;
    const int w    = tid >> 5;
    const int track0 = blockIdx.x * NT_TILE;
    const int lr = lane >> 2, c2 = (lane & 3) * 2;
    const int w16 = w * 16;

    __shared__ __align__(16) __half sh_h0[8192];   // single-buffered (phase-separated)
    __shared__ __align__(16) __half sh_h1[8192];
    __shared__ float sb0[512], sb1[512], swih0[1024];
    __shared__ float xin[12][NT_TILE], f3s[3][NT_TILE];

    for (int i = tid; i < 512; i += CTA_THREADS) { sb0[i] = g_b0c[i]; sb1[i] = g_b1c[i]; }
    for (int i = tid; i < 1024; i += CTA_THREADS) swih0[i] = W_ih0[i];
    for (int i = tid; i < 12 * NT_TILE; i += CTA_THREADS) {
        int f = i / NT_TILE, n = i % NT_TILE;
        int gt = track0 + n, b = gt / NTRK, t = gt - b * NTRK;
        xin[f][n] = tf[((size_t)b * NFEAT + 6 + f) * NTRK + t];
    }
    for (int i = tid; i < 3 * NT_TILE; i += CTA_THREADS) {
        int f = i / NT_TILE, n = i % NT_TILE;
        int gt = track0 + n, b = gt / NTRK, t = gt - b * NTRK;
        f3s[f][n] = tf[((size_t)b * NFEAT + f) * NTRK + t];
    }
    __syncthreads();

    float cst0A[16], cst0B[16], cst1A[16], cst1B[16];
#pragma unroll
    for (int i = 0; i < 16; ++i) { cst0A[i] = 0.f; cst0B[i] = 0.f; cst1A[i] = 0.f; cst1B[i] = 0.f; }

    float acc0[4][4][4];   // group A accumulators
    float acc1[4][4][4];   // group B accumulators

    // layer-0 preact init: bias + W_ih0 * x_t  (x dim = 2)
    auto l0_init = [&](float (&acc)[4][4][4], int t, int g32) {
        float bias8[4][2], wv[4][2][2];
#pragma unroll
        for (int g = 0; g < 4; ++g)
#pragma unroll
            for (int uu = 0; uu < 2; ++uu) {
                int row = g * 128 + w16 + lr + 8 * uu;
                bias8[g][uu] = sb0[row];
                wv[g][uu][0] = swih0[row * 2 + 0];
                wv[g][uu][1] = swih0[row * 2 + 1];
            }
#pragma unroll
        for (int nt = 0; nt < 4; ++nt)
#pragma unroll
            for (int dd = 0; dd < 2; ++dd) {
                int n = g32 + nt * 8 + c2 + dd;
                float x0 = xin[2 * t + 0][n], x1 = xin[2 * t + 1][n];
#pragma unroll
                for (int g = 0; g < 4; ++g)
#pragma unroll
                    for (int uu = 0; uu < 2; ++uu)
                        acc[g][nt][uu * 2 + dd] =
                            fmaf(wv[g][uu][1], x1, fmaf(wv[g][uu][0], x0, bias8[g][uu]));
            }
    };
    auto l1_init = [&](float (&acc)[4][4][4]) {
#pragma unroll
        for (int g = 0; g < 4; ++g)
#pragma unroll
            for (int uu = 0; uu < 2; ++uu) {
                float b = sb1[g * 128 + w16 + lr + 8 * uu];
#pragma unroll
                for (int nt = 0; nt < 4; ++nt) {
                    acc[g][nt][uu * 2 + 0] = b;
                    acc[g][nt][uu * 2 + 1] = b;
                }
            }
    };

#pragma unroll 1
    for (int t = 0; t < TSTEPS; ++t) {
        // ---- phase 1: G0A ; E1B(t-1) ----
        l0_init(acc0, t, 0);
        if (t > 0) {
            gemm_frag<4, 8>(acc0, P_hh0 + w * 8192, sh_h0, lane, 0);
            epi_lstm(acc1, cst1B, sh_h1, 32, w16, lr, c2);
        }
        __syncthreads();
        // ---- phase 2: G0B ; E0A ----
        l0_init(acc1, t, 32);
        if (t > 0)
            gemm_frag<4, 8>(acc1, P_hh0 + w * 8192, sh_h0, lane, 32);
        epi_lstm(acc0, cst0A, sh_h0, 0, w16, lr, c2);
        __syncthreads();
        // ---- phase 3: G1A ; E0B ----
        l1_init(acc0);
        gemm_frag<4, 8>(acc0, P_ih1 + w * 8192, sh_h0, lane, 0);
        if (t > 0)
            gemm_frag<4, 8>(acc0, P_hh1 + w * 8192, sh_h1, lane, 0);
        epi_lstm(acc1, cst0B, sh_h0, 32, w16, lr, c2);
        __syncthreads();
        // ---- phase 4: G1B ; E1A ----
        l1_init(acc1);
        gemm_frag<4, 8>(acc1, P_ih1 + w * 8192, sh_h0, lane, 32);
        if (t > 0)
            gemm_frag<4, 8>(acc1, P_hh1 + w * 8192, sh_h1, lane, 32);
        epi_lstm(acc0, cst1A, sh_h1, 0, w16, lr, c2);
        __syncthreads();
    }
    // final E1B(t=5)
    epi_lstm(acc1, cst1B, sh_h1, 32, w16, lr, c2);
    __syncthreads();

    // ---------- MLP layer 0: relu(b0 + W0[:,0:3]*f3 + W0[:,3:131]*h1) ----------
    {
        float macc[2][2][4][4];   // [group][mt][nt][4]
#pragma unroll
        for (int g = 0; g < 2; ++g)
#pragma unroll
            for (int mt = 0; mt < 2; ++mt)
#pragma unroll
                for (int du = 0; du < 2; ++du) {
                    int row = w * 32 + mt * 16 + lr + 8 * du;
                    float bv = mb0[row];
                    float w0 = mw0[row * 131 + 0];
                    float w1 = mw0[row * 131 + 1];
                    float w2 = mw0[row * 131 + 2];
#pragma unroll
                    for (int nt = 0; nt < 4; ++nt)
#pragma unroll
                        for (int dd = 0; dd < 2; ++dd) {
                            int n = g * 32 + nt * 8 + c2 + dd;
                            float a = bv;
                            a = fmaf(w0, f3s[0][n], a);
                            a = fmaf(w1, f3s[1][n], a);
                            a = fmaf(w2, f3s[2][n], a);
                            macc[g][mt][nt][du * 2 + dd] = a;
                        }
                }
        gemm_frag<2, 8>(macc[0], P_w0 + w * 4096, sh_h1, lane, 0);
        gemm_frag<2, 8>(macc[1], P_w0 + w * 4096, sh_h1, lane, 32);
        __syncthreads();                       // all h1 reads complete

        // relu -> m2 fragments: units 0..127 into sh_h0, 128..255 into sh_h1
#pragma unroll
        for (int g = 0; g < 2; ++g)
#pragma unroll
            for (int mt = 0; mt < 2; ++mt)
#pragma unroll
                for (int nt = 0; nt < 4; ++nt)
#pragma unroll
                    for (int idx = 0; idx < 4; ++idx) {
                        float v = fmaxf(macc[g][mt][nt][idx], 0.f);
                        int u = w * 32 + mt * 16 + lr + 8 * (idx >> 1);
                        int n = g * 32 + nt * 8 + c2 + (idx & 1);
                        if (u < 128) sh_h0[hb64(u, n)] = __float2half_rn(v);
                        else         sh_h1[hb64(u - 128, n)] = __float2half_rn(v);
                    }
    }
    __syncthreads();

    // ---------- MLP layer 1: out = b1 + W1 * m2 ----------
    {
        float oacc[2][2][4][4];
#pragma unroll
        for (int g = 0; g < 2; ++g)
#pragma unroll
            for (int mt = 0; mt < 2; ++mt)
#pragma unroll
                for (int du = 0; du < 2; ++du) {
                    float bv = mb1[w * 32 + mt * 16 + lr + 8 * du];
#pragma unroll
                    for (int nt = 0; nt < 4; ++nt) {
                        oacc[g][mt][nt][du * 2 + 0] = bv;
                        oacc[g][mt][nt][du * 2 + 1] = bv;
                    }
                }
        gemm_frag<2, 8>(oacc[0], P_w1 + (w * 2 + 0) * 4096, sh_h0, lane, 0);
        gemm_frag<2, 8>(oacc[0], P_w1 + (w * 2 + 1) * 4096, sh_h1, lane, 0);
        gemm_frag<2, 8>(oacc[1], P_w1 + (w * 2 + 0) * 4096, sh_h0, lane, 32);
        gemm_frag<2, 8>(oacc[1], P_w1 + (w * 2 + 1) * 4096, sh_h1, lane, 32);

#pragma unroll
        for (int g = 0; g < 2; ++g)
#pragma unroll
            for (int mt = 0; mt < 2; ++mt)
#pragma unroll
                for (int nt = 0; nt < 4; ++nt)
#pragma unroll
                    for (int idx = 0; idx < 4; ++idx) {
                        int row = w * 32 + mt * 16 + lr + 8 * (idx >> 1);
                        int n = g * 32 + nt * 8 + c2 + (idx & 1);
                        out[(size_t)(track0 + n) * HID + row] = oacc[g][mt][nt][idx];
                    }
    }
}

// ---------------- pos encoding ----------------
__global__ void pos_kernel(const float* __restrict__ tf, float* __restrict__ out)
{
    int idx = blockIdx.x * blockDim.x + threadIdx.x;
    if (idx >= NTRACK * 128) return;
    int gt = idx >> 7;
    int fi = idx & 127;
    int b = gt / NTRK, t = gt - b * NTRK;
    int coord = (fi < 64) ? 3 : 4;             // eta then phi
    float x = tf[((size_t)b * NFEAT + coord) * NTRK + t];
    int f = fi & 63;
    float p = x * g_posmul[f];
    float v = (f & 1) ? __cosf(p) : __sinf(p);
    out[(size_t)OUT_POS + (size_t)gt * 128 + fi] = v;
}

// ---------------- logpt / eta / phi passthrough ----------------
__global__ void scal_kernel(const float* __restrict__ tf, float* __restrict__ out)
{
    int gt = blockIdx.x * blockDim.x + threadIdx.x;
    if (gt >= NTRACK) return;
    int b = gt / NTRK, t = gt - b * NTRK;
    out[OUT_LOGPT + gt] = tf[((size_t)b * NFEAT + 2) * NTRK + t];
    out[OUT_ETA   + gt] = tf[((size_t)b * NFEAT + 3) * NTRK + t];
    out[OUT_PHI   + gt] = tf[((size_t)b * NFEAT + 4) * NTRK + t];
}

// ---------------- launch ----------------
extern "C" void kernel_launch(void* const* d_in, const int* in_sizes, int n_in,
                              void* d_out, int out_size)
{
    (void)in_sizes; (void)n_in; (void)out_size;
    const float* tf = (const float*)d_in[0];
    float* out = (float*)d_out;

    prep_kernel<<<128, 256>>>(
        (const float*)d_in[2],                       // W_hh0
        (const float*)d_in[3], (const float*)d_in[4],// b_ih0, b_hh0
        (const float*)d_in[5], (const float*)d_in[6],// W_ih1, W_hh1
        (const float*)d_in[7], (const float*)d_in[8],// b_ih1, b_hh1
        (const float*)d_in[9], (const float*)d_in[11]// mlp_w0, mlp_w1
    );

    lstm_mlp_kernel<<<NTRACK / NT_TILE, CTA_THREADS>>>(
        tf,
        (const float*)d_in[1],     // W_ih0
        (const float*)d_in[9],     // mlp_w0 (first 3 cols)
        (const float*)d_in[10],    // mlp_b0
        (const float*)d_in[12],    // mlp_b1
        out);

    pos_kernel<<<(NTRACK * 128 + 255) / 256, 256>>>(tf, out);
    scal_kernel<<<(NTRACK + 255) / 256, 256>>>(tf, out);
}